// round 3
// baseline (speedup 1.0000x reference)
#include <cuda_runtime.h>
#include <stdint.h>

#define HH 224
#define WW 224
#define STEPS 32
#define NIMG 24            // 8 * 3
#define NSTRIPS 12
#define RPS 19             // site rows per strip: 12*19 = 228 >= 225
#define NPLANES 5          // counts per strip <= 19 < 32

// Per-image/threshold ECC accumulators + completion counter.
// Zero-initialized at load; the last block resets them each launch, so the
// "all zero at entry" invariant holds across graph replays.
__device__ int g_ecc[NIMG * STEPS];
__device__ unsigned int g_done;

// t_k exactly as jnp.linspace(-2,2,32) in f32: t_k = fl(-2 + fl(k * fl(4/31)))
__device__ __forceinline__ float tval(int k) {
    return __fadd_rn(-2.0f, __fmul_rn((float)k, 4.0f / 31.0f));
}

// 32-bit cumulative indicator mask: bit j set iff v <= t_j. 0 for v > t_31 / inf.
__device__ __forceinline__ unsigned int mask_of(float v) {
    if (!(v <= tval(31))) return 0u;
    int k = 0;
    if (!(v <= tval(0))) {
        k = (int)__fmaf_rn(v, 7.75f, 15.5f);   // (v+2)*31/4, single rounding
        k = min(max(k, 0), 31);
        while (k > 0 && v <= tval(k - 1)) --k; // exact fixup (0-1 iters typ.)
        while (v > tval(k)) ++k;               // bounded: v <= t_31
    }
    return 0xFFFFFFFFu << k;
}

// Warp-wide 32x32 bit-matrix transpose: result bit i of lane j = input bit j of lane i.
__device__ __forceinline__ unsigned int bit_transpose32(unsigned int x, int lane) {
    #pragma unroll
    for (int d = 16; d; d >>= 1) {
        unsigned int M = (d == 16) ? 0xFFFF0000u : (d == 8) ? 0xFF00FF00u :
                         (d == 4)  ? 0xF0F0F0F0u : (d == 2) ? 0xCCCCCCCCu : 0xAAAAAAAAu;
        unsigned int y = __shfl_xor_sync(0xFFFFFFFFu, x, d);
        x = (lane & d) ? ((x & M) | ((y >> d) & ~M))
                       : ((x & ~M) | ((y << d) & M));
    }
    return x;
}

__global__ __launch_bounds__(256)
void ecc_fused_kernel(const float* __restrict__ x, float* __restrict__ out) {
    const int lane  = threadIdx.x;          // 0..31
    const int w     = threadIdx.y;          // 0..7
    const int tid   = w * 32 + lane;
    const int strip = blockIdx.x;           // 0..NSTRIPS-1
    const int img   = blockIdx.y;           // 0..23

    // Lane L of warp w loads pixel column pc = 31*w + L - 1 (lane 0 = halo).
    // Site column for lane L (L>=1) is pc; sites 0..224 covered, no duplicates.
    const int pc = 31 * w + lane - 1;
    const bool colv = (unsigned)pc < (unsigned)WW;            // pixel col in [0,224)
    const unsigned vmask = (lane >= 1 && pc <= WW) ? 0xFFFFFFFFu : 0u;

    const int r0 = strip * RPS;
    const int r1 = min(r0 + RPS, HH + 1);   // site rows [r0, r1), total 225

    // Row-walking pointer for this lane (valid only when colv).
    const float* __restrict__ pp = x + (size_t)img * (HH * WW) + pc;

    unsigned P[NPLANES], M[NPLANES];
    #pragma unroll
    for (int k = 0; k < NPLANES; ++k) { P[k] = 0u; M[k] = 0u; }

    // Previous pixel-row masks (row r0-1); row -1 => all-inf => 0.
    unsigned pmd = 0u;
    if (r0 > 0 && colv) pmd = mask_of(pp[(r0 - 1) * WW]);
    unsigned pmc = __shfl_up_sync(0xFFFFFFFFu, pmd, 1);
    if (lane == 0) pmc = 0u;

    const float* rp = pp + (size_t)r0 * WW;
    for (int i = r0; i < r1; ++i, rp += WW) {
        unsigned md = 0u;
        if (i < HH && colv) md = mask_of(*rp);
        unsigned mc = __shfl_up_sync(0xFFFFFFFFu, md, 1);
        if (lane == 0) mc = 0u;

        // a=(i-1,j-1)->pmc  b=(i-1,j)->pmd  c=(i,j-1)->mc  d=(i,j)->md
        // net per threshold in {-1,0,+1}:
        unsigned plus  = (pmc & ~(pmd | mc | md)) & vmask;
        unsigned minus = (pmd & mc & ~md) & vmask;

        // carry-save accumulate one bit per threshold column.
        // P and M chains are independent -> interleave for ILP.
        unsigned cp = plus, cm = minus, tp, tm;
        #pragma unroll
        for (int k = 0; k < NPLANES; ++k) {
            tp = P[k] & cp;  tm = M[k] & cm;
            P[k] ^= cp;      M[k] ^= cm;
            cp = tp;         cm = tm;
        }

        pmd = md; pmc = mc;
    }

    // Per-warp: transpose each plane, popc across lanes, weight by 2^k.
    // After transpose, lane j holds the warp's threshold-j column.
    int acc = 0;
    #pragma unroll
    for (int k = 0; k < NPLANES; ++k) {
        acc += (int)(__popc(bit_transpose32(P[k], lane)) << k);
        acc -= (int)(__popc(bit_transpose32(M[k], lane)) << k);
    }

    // Block combine (8 warps) then one global atomic per threshold per block.
    __shared__ int sh[STEPS];
    if (tid < STEPS) sh[tid] = 0;
    __syncthreads();
    if (acc != 0) atomicAdd(&sh[lane], acc);
    __syncthreads();
    if (tid < STEPS && sh[tid] != 0)
        atomicAdd(&g_ecc[img * STEPS + tid], sh[tid]);

    // ---- fused finalize: last block converts g_ecc -> out and resets state ----
    __shared__ unsigned int done;
    __threadfence();
    __syncthreads();
    if (tid == 0) done = atomicAdd(&g_done, 1u);
    __syncthreads();
    if (done == (unsigned)(gridDim.x * gridDim.y) - 1u) {
        __threadfence();
        for (int idx = tid; idx < NIMG * STEPS; idx += 256) {
            int v = atomicExch(&g_ecc[idx], 0);   // read + reset for next replay
            out[idx] = (float)v;
        }
        if (tid == 0) g_done = 0u;
    }
}

extern "C" void kernel_launch(void* const* d_in, const int* in_sizes, int n_in,
                              void* d_out, int out_size) {
    const float* x = (const float*)d_in[0];
    float* out = (float*)d_out;
    (void)in_sizes; (void)n_in; (void)out_size;

    dim3 grid(NSTRIPS, NIMG);
    dim3 block(32, 8);
    ecc_fused_kernel<<<grid, block>>>(x, out);
}

// round 4
// speedup vs baseline: 1.2220x; 1.2220x over previous
#include <cuda_runtime.h>
#include <stdint.h>

#define HH 224
#define WW 224
#define STEPS 32
#define NIMG 24            // 8 * 3
#define NSTRIPS 25
#define RPS 9              // site rows per strip: 25*9 = 225 exactly
#define NPLANES 4          // counts per strip <= 9 < 16

// Per-image/threshold ECC accumulators + completion counter.
// Zero-initialized at load; the last block resets them each launch, so the
// "all zero at entry" invariant holds across graph replays.
__device__ int g_ecc[NIMG * STEPS];
__device__ unsigned int g_done;

// t_k exactly as jnp.linspace(-2,2,32) in f32: t_k = fl(-2 + fl(k * fl(4/31)))
__device__ __forceinline__ float tval(int k) {
    return __fadd_rn(-2.0f, __fmul_rn((float)k, 4.0f / 31.0f));
}

// Branch-free cumulative indicator mask: bit j set iff v <= t_j (0 if v > t_31).
// Guess k ~ (v+2)*31/4 with one fma rounding; |error| < 1 bin, so one
// predicated decrement + one predicated increment make it exact w.r.t. the
// float comparisons. No divergent branches.
__device__ __forceinline__ unsigned int mask_of(float v) {
    int k = (int)__fmaf_rn(v, 7.75f, 15.5f);
    k = min(max(k, 1), 31);
    k -= (v <= tval(k - 1)) ? 1 : 0;     // if dec fired, inc below cannot
    k += (v > tval(k)) ? 1 : 0;          // k may reach 32 only when v > t_31
    unsigned int m = 0xFFFFFFFFu << min(k, 31);
    return (v <= tval(31)) ? m : 0u;     // +inf / v>t_31 -> 0
}

// Warp-wide 32x32 bit-matrix transpose: result bit i of lane j = input bit j of lane i.
__device__ __forceinline__ unsigned int bit_transpose32(unsigned int x, int lane) {
    #pragma unroll
    for (int d = 16; d; d >>= 1) {
        unsigned int M = (d == 16) ? 0xFFFF0000u : (d == 8) ? 0xFF00FF00u :
                         (d == 4)  ? 0xF0F0F0F0u : (d == 2) ? 0xCCCCCCCCu : 0xAAAAAAAAu;
        unsigned int y = __shfl_xor_sync(0xFFFFFFFFu, x, d);
        x = (lane & d) ? ((x & M) | ((y >> d) & ~M))
                       : ((x & ~M) | ((y << d) & M));
    }
    return x;
}

__global__ __launch_bounds__(256)
void ecc_fused_kernel(const float* __restrict__ x, float* __restrict__ out) {
    const int lane  = threadIdx.x;          // 0..31
    const int w     = threadIdx.y;          // 0..7
    const int tid   = w * 32 + lane;
    const int strip = blockIdx.x;           // 0..NSTRIPS-1
    const int img   = blockIdx.y;           // 0..23

    // Lane L of warp w loads pixel column pc = 31*w + L - 1 (lane 0 = halo).
    // Site column for lane L (L>=1) is pc; site cols 0..224 covered once.
    const int pc   = 31 * w + lane - 1;
    const bool colv = (unsigned)pc < (unsigned)WW;            // pixel col valid
    const unsigned vmask = (lane >= 1 && pc <= WW) ? 0xFFFFFFFFu : 0u;

    const int r0 = strip * RPS;             // site rows [r0, r0+RPS)
    const float INF = __int_as_float(0x7f800000);
    const float* __restrict__ pp = x + (size_t)img * (HH * WW) + pc;

    // ---- front-load all RPS+1 pixel-row values (MLP = 10) ----
    float vrow[RPS + 1];
    vrow[0] = (r0 > 0 && colv) ? pp[(size_t)(r0 - 1) * WW] : INF;   // halo row
    #pragma unroll
    for (int r = 0; r < RPS; ++r) {
        const int i = r0 + r;               // pixel row i (site row i uses i-1,i)
        vrow[r + 1] = (i < HH && colv) ? pp[(size_t)i * WW] : INF;
    }

    unsigned P[NPLANES], M[NPLANES];
    #pragma unroll
    for (int k = 0; k < NPLANES; ++k) { P[k] = 0u; M[k] = 0u; }

    unsigned pmd = mask_of(vrow[0]);
    unsigned pmc = __shfl_up_sync(0xFFFFFFFFu, pmd, 1);
    pmc = (lane == 0) ? 0u : pmc;

    #pragma unroll
    for (int r = 0; r < RPS; ++r) {
        unsigned md = mask_of(vrow[r + 1]);
        unsigned mc = __shfl_up_sync(0xFFFFFFFFu, md, 1);
        mc = (lane == 0) ? 0u : mc;

        // a=(i-1,j-1)->pmc  b=(i-1,j)->pmd  c=(i,j-1)->mc  d=(i,j)->md
        // net per threshold in {-1,0,+1}:
        unsigned plus  = (pmc & ~(pmd | mc | md)) & vmask;
        unsigned minus = (pmd & mc & ~md) & vmask;

        // carry-save accumulate; P and M chains independent -> ILP.
        unsigned cp = plus, cm = minus, tp, tm;
        #pragma unroll
        for (int k = 0; k < NPLANES; ++k) {
            tp = P[k] & cp;  tm = M[k] & cm;
            P[k] ^= cp;      M[k] ^= cm;
            cp = tp;         cm = tm;
        }
        pmd = md; pmc = mc;
    }

    // Per-warp: transpose each plane, popc across lanes, weight by 2^k.
    // After transpose, lane j holds this warp's threshold-j bit column.
    int acc = 0;
    #pragma unroll
    for (int k = 0; k < NPLANES; ++k) {
        acc += (int)(__popc(bit_transpose32(P[k], lane)) << k);
        acc -= (int)(__popc(bit_transpose32(M[k], lane)) << k);
    }

    // Block combine (8 warps) then one global atomic per threshold per block.
    __shared__ int sh[STEPS];
    if (tid < STEPS) sh[tid] = 0;
    __syncthreads();
    if (acc != 0) atomicAdd(&sh[lane], acc);
    __syncthreads();
    if (tid < STEPS && sh[tid] != 0)
        atomicAdd(&g_ecc[img * STEPS + tid], sh[tid]);

    // ---- fused finalize: last block converts g_ecc -> out and resets state ----
    __shared__ unsigned int done;
    __threadfence();
    __syncthreads();
    if (tid == 0) done = atomicAdd(&g_done, 1u);
    __syncthreads();
    if (done == (unsigned)(gridDim.x * gridDim.y) - 1u) {
        __threadfence();
        for (int idx = tid; idx < NIMG * STEPS; idx += 256) {
            int v = atomicExch(&g_ecc[idx], 0);   // read + reset for next replay
            out[idx] = (float)v;
        }
        if (tid == 0) g_done = 0u;
    }
}

extern "C" void kernel_launch(void* const* d_in, const int* in_sizes, int n_in,
                              void* d_out, int out_size) {
    const float* x = (const float*)d_in[0];
    float* out = (float*)d_out;
    (void)in_sizes; (void)n_in; (void)out_size;

    dim3 grid(NSTRIPS, NIMG);
    dim3 block(32, 8);
    ecc_fused_kernel<<<grid, block>>>(x, out);
}

// round 5
// speedup vs baseline: 1.9096x; 1.5627x over previous
#include <cuda_runtime.h>
#include <stdint.h>

#define HH 224
#define WW 224
#define STEPS 32
#define NIMG 24            // 8 * 3
#define NSTRIPS 15
#define RPS 15             // site rows per strip: 15*15 = 225 exactly
#define NPLANES 4          // per-strip counts <= 15 -> 4 bit-planes

// Per-image/threshold ECC accumulators + completion counter.
// Zero-initialized at load; the last block resets them each launch, so the
// "all zero at entry" invariant holds across graph replays.
__device__ int g_ecc[NIMG * STEPS];
__device__ unsigned int g_done;

// Exact cumulative indicator mask: bit j set iff v <= t_j, where
// t_j = fl(-2 + fl(j * fl(4/31))) (bit-identical to jnp.linspace(-2,2,32) f32).
// Guess g = (v+2)*7.75 + 1/64 bias: at a boundary t_j, |g - (j + 1/64)| < 1e-4,
// so floor(clamp(g)) is k* or k*-1; one compare v > t_k fixes it exactly.
// k == 32 (v > t_31 = 2.0f, incl. +inf) -> 64-bit shift yields mask 0.
__device__ __forceinline__ unsigned int mask_of(float v) {
    float g = __fmaf_rn(v, 7.75f, 15.515625f);
    g = fminf(fmaxf(g, 0.0f), 31.0f);
    int k = (int)g;
    float t = __fadd_rn(-2.0f, __fmul_rn((float)k, 4.0f / 31.0f));
    k += (v > t) ? 1 : 0;
    return (unsigned int)(0xFFFFFFFFull << k);
}

__global__ __launch_bounds__(256)
void ecc_fused_kernel(const float* __restrict__ x, float* __restrict__ out) {
    const int lane  = threadIdx.x;          // 0..31
    const int w     = threadIdx.y;          // 0..7
    const int tid   = w * 32 + lane;
    const int strip = blockIdx.x;           // 0..NSTRIPS-1
    const int img   = blockIdx.y;           // 0..23

    // Lane L of warp w owns pixel column pc = 31*w + L - 1 (lane 0 = halo dup).
    // Site column for lane L>=1 is pc; cols 0..224 covered exactly once
    // (invalid lanes contribute 0 automatically: their pmc/mc/pmd factors are 0).
    const int pc    = 31 * w + lane - 1;
    const bool colv = (unsigned)pc < (unsigned)WW;
    const float INF = __int_as_float(0x7f800000);

    const int r0 = strip * RPS;             // site rows [r0, r0+RPS)
    const float* __restrict__ q = x + img * (HH * WW) + (colv ? pc : 0);

    // ---- front-load the RPS+1 pixel rows (halo r0-1 .. r0+RPS-1), MLP=16 ----
    float vrow[RPS + 1];
    #pragma unroll
    for (int t = 0; t < RPS + 1; ++t) {
        const int pr = r0 - 1 + t;                    // pixel row
        const bool ok = colv && ((unsigned)pr < (unsigned)HH);
        vrow[t] = ok ? __ldg(q + pr * WW) : INF;
    }

    unsigned P[NPLANES], M[NPLANES];
    #pragma unroll
    for (int k = 0; k < NPLANES; ++k) { P[k] = 0u; M[k] = 0u; }

    unsigned pmd = mask_of(vrow[0]);
    unsigned pmc = __shfl_up_sync(0xFFFFFFFFu, pmd, 1);
    pmc = (lane == 0) ? 0u : pmc;

    #pragma unroll
    for (int r = 0; r < RPS; ++r) {
        unsigned md = mask_of(vrow[r + 1]);
        unsigned mc = __shfl_up_sync(0xFFFFFFFFu, md, 1);
        mc = (lane == 0) ? 0u : mc;

        // a=(i-1,j-1)->pmc  b=(i-1,j)->pmd  c=(i,j-1)->mc  d=(i,j)->md
        const unsigned u     = pmd | mc | md;   // 1 LOP3
        const unsigned plus  = pmc & ~u;        // vertex born & no edge covers it
        const unsigned minus = pmd & mc & ~md;  // both edges, face not yet

        // carry-save accumulate; P and M chains independent -> ILP.
        unsigned cp = plus, cm = minus, tp, tm;
        #pragma unroll
        for (int k = 0; k < NPLANES; ++k) {
            tp = P[k] & cp;  tm = M[k] & cm;
            P[k] ^= cp;      M[k] ^= cm;
            cp = tp;         cm = tm;
        }
        pmd = md; pmc = mc;
    }

    // ---- per-warp 32x32 bit transpose (3 instr/stage) + weighted popc ----
    unsigned keepm[5]; int amt[5];
    {
        const unsigned Ms[5] = {0xFFFF0000u, 0xFF00FF00u, 0xF0F0F0F0u,
                                0xCCCCCCCCu, 0xAAAAAAAAu};
        const int ds[5] = {16, 8, 4, 2, 1};
        #pragma unroll
        for (int s = 0; s < 5; ++s) {
            const bool b = (lane & ds[s]) != 0;
            keepm[s] = b ? Ms[s] : ~Ms[s];
            amt[s]   = b ? ds[s] : 32 - ds[s];
        }
    }
    int acc = 0;
    #pragma unroll
    for (int k = 0; k < 2 * NPLANES; ++k) {
        unsigned v = (k < NPLANES) ? P[k] : M[k - NPLANES];
        const int ds[5] = {16, 8, 4, 2, 1};
        #pragma unroll
        for (int s = 0; s < 5; ++s) {
            unsigned y = __shfl_xor_sync(0xFFFFFFFFu, v, ds[s]);
            unsigned r = __funnelshift_r(y, y, amt[s]);   // rotate == both shift arms under mask
            v = (v & keepm[s]) | (r & ~keepm[s]);         // 1 LOP3
        }
        const int wgt = __popc(v) << (k < NPLANES ? k : k - NPLANES);
        acc += (k < NPLANES) ? wgt : -wgt;
    }
    // lane j now holds this warp's net count for threshold j.

    // ---- block combine (no atomics) + one global atomic per threshold ----
    __shared__ int sh[8][STEPS];
    sh[w][lane] = acc;
    __syncthreads();
    if (w == 0) {
        int s = 0;
        #pragma unroll
        for (int ww = 0; ww < 8; ++ww) s += sh[ww][lane];
        if (s != 0) atomicAdd(&g_ecc[img * STEPS + lane], s);
    }

    // ---- fused finalize: last block converts g_ecc -> out and resets state ----
    __shared__ unsigned int done;
    __threadfence();
    __syncthreads();
    if (tid == 0) done = atomicAdd(&g_done, 1u);
    __syncthreads();
    if (done == (unsigned)(NSTRIPS * NIMG) - 1u) {
        __threadfence();
        for (int idx = tid; idx < NIMG * STEPS; idx += 256) {
            int v = atomicExch(&g_ecc[idx], 0);   // read + reset for next replay
            out[idx] = (float)v;
        }
        if (tid == 0) g_done = 0u;
    }
}

extern "C" void kernel_launch(void* const* d_in, const int* in_sizes, int n_in,
                              void* d_out, int out_size) {
    const float* x = (const float*)d_in[0];
    float* out = (float*)d_out;
    (void)in_sizes; (void)n_in; (void)out_size;

    dim3 grid(NSTRIPS, NIMG);
    dim3 block(32, 8);
    ecc_fused_kernel<<<grid, block>>>(x, out);
}

// round 7
// speedup vs baseline: 1.9494x; 1.0208x over previous
#include <cuda_runtime.h>
#include <stdint.h>

#define HH 224
#define WW 224
#define STEPS 32
#define NIMG 24            // 8 * 3
#define NSTRIPS 25
#define RPS 9              // site rows per strip: 25*9 = 225 exactly
#define NPLANES 4          // per-strip counts <= 9 -> 4 bit-planes

// Per-image/threshold ECC accumulators + completion counter.
// Zero-initialized at load; the last block resets them each launch, so the
// "all zero at entry" invariant holds across graph replays.
__device__ int g_ecc[NIMG * STEPS];
__device__ unsigned int g_done;

// Exact cumulative indicator mask: bit j set iff v <= t_j, where
// t_j = fl(-2 + fl(j * fl(4/31))) (bit-identical to jnp.linspace(-2,2,32) f32).
// Guess g = (v+2)*7.75 + 1/64 bias: at a boundary t_j, |g - (j + 1/64)| < 1e-4,
// so floor(clamp(g)) is k* or k*-1; one compare v > t_k fixes it exactly.
// k == 32 (v > t_31 = 2.0f, incl. +inf) -> 64-bit shift yields mask 0.
__device__ __forceinline__ unsigned int mask_of(float v) {
    float g = __fmaf_rn(v, 7.75f, 15.515625f);
    g = fminf(fmaxf(g, 0.0f), 31.0f);
    int k = (int)g;
    float t = __fadd_rn(-2.0f, __fmul_rn((float)k, 4.0f / 31.0f));
    k += (v > t) ? 1 : 0;
    return (unsigned int)(0xFFFFFFFFull << k);
}

__global__ __launch_bounds__(256, 4)   // 64-reg budget: no spills, 4 blocks/SM
void ecc_fused_kernel(const float* __restrict__ x, float* __restrict__ out) {
    const int lane  = threadIdx.x;          // 0..31
    const int w     = threadIdx.y;          // 0..7
    const int tid   = w * 32 + lane;
    const int strip = blockIdx.x;           // 0..NSTRIPS-1
    const int img   = blockIdx.y;           // 0..23

    // Lane L of warp w owns pixel column pc = 31*w + L - 1 (lane 0 = halo dup).
    // Site column for lane L>=1 is pc; cols 0..224 covered exactly once
    // (invalid lanes contribute 0 automatically: their pmc/mc/pmd factors are 0).
    const int pc    = 31 * w + lane - 1;
    const bool colv = (unsigned)pc < (unsigned)WW;
    const float INF = __int_as_float(0x7f800000);

    const int r0 = strip * RPS;             // site rows [r0, r0+RPS)
    const float* __restrict__ q = x + img * (HH * WW) + (colv ? pc : 0);

    // ---- front-load the RPS+1 pixel rows (halo r0-1 .. r0+RPS-1), MLP=10 ----
    float vrow[RPS + 1];
    #pragma unroll
    for (int t = 0; t < RPS + 1; ++t) {
        const int pr = r0 - 1 + t;                    // pixel row
        const bool ok = colv && ((unsigned)pr < (unsigned)HH);
        vrow[t] = ok ? __ldg(q + pr * WW) : INF;
    }

    unsigned P[NPLANES], M[NPLANES];
    #pragma unroll
    for (int k = 0; k < NPLANES; ++k) { P[k] = 0u; M[k] = 0u; }

    unsigned pmd = mask_of(vrow[0]);
    unsigned pmc = __shfl_up_sync(0xFFFFFFFFu, pmd, 1);
    pmc = (lane == 0) ? 0u : pmc;

    #pragma unroll
    for (int r = 0; r < RPS; ++r) {
        unsigned md = mask_of(vrow[r + 1]);
        unsigned mc = __shfl_up_sync(0xFFFFFFFFu, md, 1);
        mc = (lane == 0) ? 0u : mc;

        // a=(i-1,j-1)->pmc  b=(i-1,j)->pmd  c=(i,j-1)->mc  d=(i,j)->md
        const unsigned u     = pmd | mc | md;   // 1 LOP3
        const unsigned plus  = pmc & ~u;        // vertex born & no edge covers it
        const unsigned minus = pmd & mc & ~md;  // both edges, face not yet

        // carry-save accumulate; P and M chains independent -> ILP.
        unsigned cp = plus, cm = minus, tp, tm;
        #pragma unroll
        for (int k = 0; k < NPLANES; ++k) {
            tp = P[k] & cp;  tm = M[k] & cm;
            P[k] ^= cp;      M[k] ^= cm;
            cp = tp;         cm = tm;
        }
        pmd = md; pmc = mc;
    }

    // ---- per-warp 32x32 bit transpose (3 instr/stage) + weighted popc ----
    unsigned keepm[5]; int amt[5];
    {
        const unsigned Ms[5] = {0xFFFF0000u, 0xFF00FF00u, 0xF0F0F0F0u,
                                0xCCCCCCCCu, 0xAAAAAAAAu};
        const int ds[5] = {16, 8, 4, 2, 1};
        #pragma unroll
        for (int s = 0; s < 5; ++s) {
            const bool b = (lane & ds[s]) != 0;
            keepm[s] = b ? Ms[s] : ~Ms[s];
            amt[s]   = b ? ds[s] : 32 - ds[s];
        }
    }
    int acc = 0;
    #pragma unroll
    for (int k = 0; k < 2 * NPLANES; ++k) {
        unsigned v = (k < NPLANES) ? P[k] : M[k - NPLANES];
        const int ds[5] = {16, 8, 4, 2, 1};
        #pragma unroll
        for (int s = 0; s < 5; ++s) {
            unsigned y = __shfl_xor_sync(0xFFFFFFFFu, v, ds[s]);
            unsigned r = __funnelshift_r(y, y, amt[s]);   // rotate == both shift arms under mask
            v = (v & keepm[s]) | (r & ~keepm[s]);         // 1 LOP3
        }
        const int wgt = __popc(v) << (k < NPLANES ? k : k - NPLANES);
        acc += (k < NPLANES) ? wgt : -wgt;
    }
    // lane j now holds this warp's net count for threshold j.

    // ---- block combine (no atomics) + one global atomic per threshold ----
    __shared__ int sh[8][STEPS];
    sh[w][lane] = acc;
    __syncthreads();
    if (w == 0) {
        int s = 0;
        #pragma unroll
        for (int ww = 0; ww < 8; ++ww) s += sh[ww][lane];
        if (s != 0) atomicAdd(&g_ecc[img * STEPS + lane], s);
    }

    // ---- fused finalize: last block converts g_ecc -> out and resets state ----
    __shared__ unsigned int done;
    __threadfence();
    __syncthreads();
    if (tid == 0) done = atomicAdd(&g_done, 1u);
    __syncthreads();
    if (done == (unsigned)(NSTRIPS * NIMG) - 1u) {
        __threadfence();
        for (int idx = tid; idx < NIMG * STEPS; idx += 256) {
            int v = atomicExch(&g_ecc[idx], 0);   // read + reset for next replay
            out[idx] = (float)v;
        }
        if (tid == 0) g_done = 0u;
    }
}

extern "C" void kernel_launch(void* const* d_in, const int* in_sizes, int n_in,
                              void* d_out, int out_size) {
    const float* x = (const float*)d_in[0];
    float* out = (float*)d_out;
    (void)in_sizes; (void)n_in; (void)out_size;

    dim3 grid(NSTRIPS, NIMG);
    dim3 block(32, 8);
    ecc_fused_kernel<<<grid, block>>>(x, out);
}